// round 13
// baseline (speedup 1.0000x reference)
#include <cuda_runtime.h>
#include <cuda_bf16.h>
#include <cstdint>

// ---------------------------------------------------------------------------
// SimpleLSTM on GB300 (plain sm_103 PTX) — round 13:
//   lstm: HMMA recurrence (r11 mechanics) with TWO independent batch groups
//   per CTA sharing the same W A-fragments. The L2 exchange latency of one
//   group hides under the other group's MMA+epilogue; poll loads are issued
//   one half-iteration early, so fills hit on the first check.
//   table: bf16-split HMMA GEMM + split_kernel (r11, unchanged).
// ---------------------------------------------------------------------------

#define NB    128
#define LSEQ  2048
#define HDIM  256
#define EMB   256
#define VOC   32000
#define G3    768
#define NT    256

__device__ float    g_T[VOC * G3];          // token-gate table (~98.3 MB)
__device__ float    g_Hbuf[2][NB * HDIM];   // H double buffer (tagged values)
__device__ uint32_t g_EhG[VOC * 128];       // E hi split, bf16x2 words
__device__ uint32_t g_ElG[VOC * 128];       // E lo split
__device__ uint32_t g_WhG[G3 * 128];        // W_x hi split (live gate rows)
__device__ uint32_t g_WlG[G3 * 128];        // W_x lo split

// ---------------------------------------------------------------------------
// helpers
// ---------------------------------------------------------------------------
__device__ __forceinline__ float4 ldv4_volatile(const float* p)
{
    float4 v;
    asm volatile("ld.volatile.global.v4.f32 {%0, %1, %2, %3}, [%4];"
                 : "=f"(v.x), "=f"(v.y), "=f"(v.z), "=f"(v.w) : "l"(p)
                 : "memory");
    return v;
}

__device__ __forceinline__ float sig_fast(float x)
{
    return __fdividef(1.0f, 1.0f + __expf(-x));
}

__device__ __forceinline__ float tanh_fast(float x)
{
    return __fdividef(2.0f, 1.0f + __expf(-2.0f * x)) - 1.0f;
}

// split a float2 (consecutive k pair) into bf16x2 hi and lo b32 values.
__device__ __forceinline__ void split2(float2 f, uint32_t& hi, uint32_t& lo)
{
    __nv_bfloat16 h0 = __float2bfloat16_rn(f.x);
    __nv_bfloat16 h1 = __float2bfloat16_rn(f.y);
    __nv_bfloat16 l0 = __float2bfloat16_rn(f.x - __bfloat162float(h0));
    __nv_bfloat16 l1 = __float2bfloat16_rn(f.y - __bfloat162float(h1));
    __nv_bfloat162 ph = __halves2bfloat162(h0, h1);
    __nv_bfloat162 pl = __halves2bfloat162(l0, l1);
    hi = *(uint32_t*)&ph;
    lo = *(uint32_t*)&pl;
}

__device__ __forceinline__ void mma16816(float& c0, float& c1, float& c2, float& c3,
                                         uint32_t a0, uint32_t a1, uint32_t a2, uint32_t a3,
                                         uint32_t b0, uint32_t b1)
{
    asm volatile(
        "mma.sync.aligned.m16n8k16.row.col.f32.bf16.bf16.f32 "
        "{%0,%1,%2,%3}, {%4,%5,%6,%7}, {%8,%9}, {%0,%1,%2,%3};"
        : "+f"(c0), "+f"(c1), "+f"(c2), "+f"(c3)
        : "r"(a0), "r"(a1), "r"(a2), "r"(a3), "r"(b0), "r"(b1));
}

__device__ __forceinline__ int grow_of(int g)   // live-gate row -> W row
{
    int gate = g >> 8, jj = g & 255;
    return (gate == 0 ? 0 : (gate == 1 ? 512 : 768)) + jj;
}

// ---------------------------------------------------------------------------
// Kernel 0: split E and W_x (input half, live gate rows) into bf16 hi/lo.
// ---------------------------------------------------------------------------
__global__ void split_kernel(const float* __restrict__ E,
                             const float* __restrict__ Ww)
{
    int idx = blockIdx.x * 256 + threadIdx.x;
    uint32_t h0, l0, h1, l1;
    if (idx < VOC * 64) {
        int row = idx >> 6, f4 = idx & 63;
        float4 e = *(const float4*)(E + row * EMB + f4 * 4);
        split2(make_float2(e.x, e.y), h0, l0);
        split2(make_float2(e.z, e.w), h1, l1);
        *(uint2*)&g_EhG[row * 128 + f4 * 2] = make_uint2(h0, h1);
        *(uint2*)&g_ElG[row * 128 + f4 * 2] = make_uint2(l0, l1);
    } else {
        int widx = idx - VOC * 64;
        int row = widx >> 6, f4 = widx & 63;      // row = live gate idx 0..767
        int grow = grow_of(row);
        float4 w = *(const float4*)(Ww + grow * 512 + 256 + f4 * 4);
        split2(make_float2(w.x, w.y), h0, l0);
        split2(make_float2(w.z, w.w), h1, l1);
        *(uint2*)&g_WhG[row * 128 + f4 * 2] = make_uint2(h0, h1);
        *(uint2*)&g_WlG[row * 128 + f4 * 2] = make_uint2(l0, l1);
    }
}

// ---------------------------------------------------------------------------
// Kernel 1: token table GEMM via HMMA (M=32000, N=768, K=256), 64x64 tiles.
// ---------------------------------------------------------------------------
__global__ void __launch_bounds__(256)
table_kernel(const float* __restrict__ Wb)
{
    __shared__ uint32_t Eh[64 * 36], El[64 * 36];
    __shared__ uint32_t Wh[64 * 36], Wl[64 * 36];

    const int tid  = threadIdx.x;
    const int v0   = blockIdx.x * 64;
    const int g0   = blockIdx.y * 64;
    const int wid  = tid >> 5, lane = tid & 31;
    const int gid  = lane >> 2, tig = lane & 3;
    const int m0   = (wid & 3) * 16;
    const int n0   = (wid >> 2) * 32;

    float acc[4][4];
#pragma unroll
    for (int i = 0; i < 4; i++)
#pragma unroll
        for (int j = 0; j < 4; j++) acc[i][j] = 0.0f;

    for (int c = 0; c < 4; c++) {          // K chunk of 64
#pragma unroll
        for (int it = 0; it < 8; it++) {
            int idx = tid + it * 256;       // 0..2047
            int buf = idx >> 9, rem = idx & 511;
            int row = rem >> 3, w4 = rem & 7;
            const uint32_t* src;
            uint32_t* dst;
            if (buf == 0)      { src = &g_EhG[(v0 + row) * 128]; dst = Eh; }
            else if (buf == 1) { src = &g_ElG[(v0 + row) * 128]; dst = El; }
            else if (buf == 2) { src = &g_WhG[(g0 + row) * 128]; dst = Wh; }
            else               { src = &g_WlG[(g0 + row) * 128]; dst = Wl; }
            uint4 v = *(const uint4*)(src + c * 32 + w4 * 4);
            *(uint4*)(dst + row * 36 + w4 * 4) = v;
        }
        __syncthreads();

#pragma unroll
        for (int ktL = 0; ktL < 4; ktL++) {
            int kw = ktL * 8 + tig;
            uint32_t ah0 = Eh[(m0 + gid) * 36 + kw];
            uint32_t ah1 = Eh[(m0 + gid + 8) * 36 + kw];
            uint32_t ah2 = Eh[(m0 + gid) * 36 + kw + 4];
            uint32_t ah3 = Eh[(m0 + gid + 8) * 36 + kw + 4];
            uint32_t al0 = El[(m0 + gid) * 36 + kw];
            uint32_t al1 = El[(m0 + gid + 8) * 36 + kw];
            uint32_t al2 = El[(m0 + gid) * 36 + kw + 4];
            uint32_t al3 = El[(m0 + gid + 8) * 36 + kw + 4];
#pragma unroll
            for (int nn = 0; nn < 4; nn++) {
                int wr = (n0 + nn * 8 + gid) * 36 + kw;
                uint32_t bh0 = Wh[wr], bh1 = Wh[wr + 4];
                uint32_t bl0 = Wl[wr], bl1 = Wl[wr + 4];
                mma16816(acc[nn][0], acc[nn][1], acc[nn][2], acc[nn][3],
                         ah0, ah1, ah2, ah3, bh0, bh1);
                mma16816(acc[nn][0], acc[nn][1], acc[nn][2], acc[nn][3],
                         ah0, ah1, ah2, ah3, bl0, bl1);
                mma16816(acc[nn][0], acc[nn][1], acc[nn][2], acc[nn][3],
                         al0, al1, al2, al3, bh0, bh1);
            }
        }
        __syncthreads();
    }

#pragma unroll
    for (int nn = 0; nn < 4; nn++) {
        int g  = g0 + n0 + nn * 8 + tig * 2;
        float b0 = Wb[grow_of(g)];
        float b1 = Wb[grow_of(g + 1)];
        int vA = v0 + m0 + gid, vB = vA + 8;
        *(float2*)&g_T[vA * G3 + g] = make_float2(acc[nn][0] + b0, acc[nn][1] + b1);
        *(float2*)&g_T[vB * G3 + g] = make_float2(acc[nn][2] + b0, acc[nn][3] + b1);
    }
}

// ---------------------------------------------------------------------------
// Kernel 2: persistent recurrence, two interleaved batch groups per CTA.
//   grid = 64 CTAs: gp = blockIdx.x>>3 (group pair), ct = blockIdx.x&7.
//   Group 0 rows: 8*gp .. +7;  group 1 rows: 64 + 8*gp .. +7. Same cols.
// ---------------------------------------------------------------------------

#define KTW   132           // words per k-tile slot (128 + 4 pad)
#define BFH   (16 * KTW)

__global__ void __launch_bounds__(NT, 1)
lstm_kernel(const void* __restrict__ Xraw,
            const float* __restrict__ Ww,
            float* __restrict__ out)
{
    __shared__ uint32_t Bf[BFH];           // B fragments (shared across halves)
    __shared__ float    Gsm2[96 * 9];      // G staging, stride 9
    __shared__ float    Csm[512];          // C state, per group
    __shared__ int      tokb[4][8];        // [grp*2 + parity][row]

    const int tid  = threadIdx.x;
    const int wid  = tid >> 5;
    const int lane = tid & 31;
    const int gp   = blockIdx.x >> 3;      // group pair 0..7
    const int ct   = blockIdx.x & 7;
    const int j0   = ct * 32;
    const int rbA  = gp * 8;               // group 0 first row
    const int rbB  = 64 + gp * 8;          // group 1 first row

    const int gid = lane >> 2;
    const int tig = lane & 3;

    // --- int64 vs int32 token buffer detection ----------------------------
    const int* Xi = (const int*)Xraw;
    bool is64 = true;
#pragma unroll
    for (int i = 0; i < 16; i++)
        if (Xi[2 * i + 1] != 0) is64 = false;
    const long long* Xl = (const long long*)Xraw;

    // --- init ----------------------------------------------------------------
    for (int i = tid; i < BFH; i += NT) Bf[i] = 0u;
    Csm[tid] = 0.0f;
    Csm[tid + 256] = 0.0f;
    if (tid < 8) {
        tokb[0][tid] = is64 ? (int)Xl[(rbA + tid) * LSEQ] : Xi[(rbA + tid) * LSEQ];
        tokb[2][tid] = is64 ? (int)Xl[(rbB + tid) * LSEQ] : Xi[(rbB + tid) * LSEQ];
    }

    // --- build W A-fragments in registers (warps 0..5); shared by both groups
    uint32_t A1[16][4], A2[16][4];
    if (wid < 6) {
        int m0 = wid * 16 + gid, m1 = m0 + 8;
        int ga = m0 >> 5, ja = m0 & 31;
        int gb = m1 >> 5, jb = m1 & 31;
        int grow0 = (ga == 0 ? 0 : (ga == 1 ? 512 : 768)) + j0 + ja;
        int grow1 = (gb == 0 ? 0 : (gb == 1 ? 512 : 768)) + j0 + jb;
#pragma unroll
        for (int kt = 0; kt < 16; kt++) {
            int k = kt * 16 + tig * 2;
            float2 f;
            f = __ldg((const float2*)(Ww + grow0 * 512 + k));
            split2(f, A1[kt][0], A2[kt][0]);
            f = __ldg((const float2*)(Ww + grow1 * 512 + k));
            split2(f, A1[kt][1], A2[kt][1]);
            f = __ldg((const float2*)(Ww + grow0 * 512 + k + 8));
            split2(f, A1[kt][2], A2[kt][2]);
            f = __ldg((const float2*)(Ww + grow1 * 512 + k + 8));
            split2(f, A1[kt][3], A2[kt][3]);
        }
    }
    __syncthreads();

    // --- fill mapping (all 8 warps; producer rank = wid) --------------------
    const int kq = wid;
    const int fq = lane & 7;
    const int r0 = lane >> 3;           // rows 0..3
    const int r1 = r0 + 4;              // rows 4..7
    const int fkt  = kq * 2 + (fq >> 2);
    const int freg = (fq >> 1) & 1;
    const int ftig = (fq & 1) * 2;
    uint2* B2 = (uint2*)Bf;
    const int u0a = fkt * (KTW / 2) + (r0 * 4 + ftig) * 2 + freg;
    const int u0b = fkt * (KTW / 2) + (r0 * 4 + ftig + 1) * 2 + freg;
    const int u1a = fkt * (KTW / 2) + (r1 * 4 + ftig) * 2 + freg;
    const int u1b = fkt * (KTW / 2) + (r1 * 4 + ftig + 1) * 2 + freg;
    const int off0 = r0 * HDIM + kq * 32 + fq * 4;   // + rb*HDIM at use
    const int off1 = r1 * HDIM + kq * 32 + fq * 4;

    const int er = tid >> 5, ej = lane;  // epilogue element (row, col)

    float4 pv0, pv1;                     // in-flight poll values (next half)

    for (int t = 0; t < LSEQ; t++) {
#pragma unroll
        for (int g = 0; g < 2; g++) {
            const int rbg = (g == 0) ? rbA : rbB;
            const int cur = t & 1, nxt = cur ^ 1;

            // ---- Gx prefetch (lands during MMA) ----------------------------
            const float* Tr = g_T + (long long)tokb[g * 2 + cur][er] * G3
                              + j0 + ej;
            float gxF = __ldg(Tr);
            float gxO = __ldg(Tr + 256);
            float gxH = __ldg(Tr + 512);

            if (tid < 8 && t + 1 < LSEQ)
                tokb[g * 2 + nxt][tid] =
                    is64 ? (int)Xl[(rbg + tid) * LSEQ + t + 1]
                         : Xi[(rbg + tid) * LSEQ + t + 1];

            // ---- fill: check in-flight polls (normally ready), STS ----------
            if (t > 0) {
                const float cr = 4.0f + 8.0f * (float)(((t - 1) >> 1) & 3);
                bool d0 = fabsf(pv0.x - cr) < 2.0f;
                bool d1 = fabsf(pv1.x - cr) < 2.0f;
                if (!(d0 && d1)) {
                    const float* hb = g_Hbuf[cur] + rbg * HDIM;
                    do {
                        if (!d0) { pv0 = ldv4_volatile(hb + off0);
                                   d0 = fabsf(pv0.x - cr) < 2.0f; }
                        if (!d1) { pv1 = ldv4_volatile(hb + off1);
                                   d1 = fabsf(pv1.x - cr) < 2.0f; }
                    } while (!(d0 && d1));
                }
                pv0.x -= cr; pv0.y -= cr; pv0.z -= cr; pv0.w -= cr;
                pv1.x -= cr; pv1.y -= cr; pv1.z -= cr; pv1.w -= cr;
                uint32_t h0, l0, h1, l1;
                split2(make_float2(pv0.x, pv0.y), h0, l0);
                split2(make_float2(pv0.z, pv0.w), h1, l1);
                B2[u0a] = make_uint2(h0, l0);
                B2[u0b] = make_uint2(h1, l1);
                split2(make_float2(pv1.x, pv1.y), h0, l0);
                split2(make_float2(pv1.z, pv1.w), h1, l1);
                B2[u1a] = make_uint2(h0, l0);
                B2[u1b] = make_uint2(h1, l1);
            }
            __syncthreads();   // (1) Bf ready (also fences prior Gsm2 readers)

            // ---- HMMA: warps 0..5, 16 k-tiles x 3 split terms ----------------
            if (wid < 6) {
                float cA0 = 0.f, cA1 = 0.f, cA2 = 0.f, cA3 = 0.f;
                float cB0 = 0.f, cB1 = 0.f, cB2 = 0.f, cB3 = 0.f;
                float cC0 = 0.f, cC1 = 0.f, cC2 = 0.f, cC3 = 0.f;
#pragma unroll
                for (int kt = 0; kt < 16; kt++) {
                    uint4 b = *(const uint4*)&Bf[kt * KTW + lane * 4];
                    mma16816(cA0, cA1, cA2, cA3,
                             A1[kt][0], A1[kt][1], A1[kt][2], A1[kt][3], b.x, b.z);
                    mma16816(cB0, cB1, cB2, cB3,
                             A1[kt][0], A1[kt][1], A1[kt][2], A1[kt][3], b.y, b.w);
                    mma16816(cC0, cC1, cC2, cC3,
                             A2[kt][0], A2[kt][1], A2[kt][2], A2[kt][3], b.x, b.z);
                }
                int m0 = wid * 16 + gid, m1 = m0 + 8;
                Gsm2[m0 * 9 + tig * 2]     = cA0 + cB0 + cC0;
                Gsm2[m0 * 9 + tig * 2 + 1] = cA1 + cB1 + cC1;
                Gsm2[m1 * 9 + tig * 2]     = cA2 + cB2 + cC2;
                Gsm2[m1 * 9 + tig * 2 + 1] = cA3 + cB3 + cC3;
            }

            // ---- issue poll loads for the NEXT half (hide RTT under epilogue)
            {
                int tn = (g == 0) ? t : t + 1;     // step the next half consumes
                if (!(t == 0 && g == 0) && tn < LSEQ) {
                    const int rbn = (g == 0) ? rbB : rbA;
                    const float* hbn = g_Hbuf[tn & 1] + rbn * HDIM;
                    pv0 = ldv4_volatile(hbn + off0);
                    pv1 = ldv4_volatile(hbn + off1);
                }
            }
            __syncthreads();   // (2) Gsm2 ready

            // ---- epilogue: gates, C, H_new (tagged store) ---------------------
            {
                const float cw = 4.0f + 8.0f * (float)((t >> 1) & 3);
                float gF = gxF + Gsm2[ej * 9 + er];
                float gO = gxO + Gsm2[(32 + ej) * 9 + er];
                float gH = gxH + Gsm2[(64 + ej) * 9 + er];
                float F  = sig_fast(gF);
                float O  = sig_fast(gO);
                float Ht = tanh_fast(gH);
                float c  = F * Csm[g * 256 + tid] + O * Ht;   // faithful: uses O
                Csm[g * 256 + tid] = c;
                float hn = O * tanh_fast(c);
                __stcg(g_Hbuf[nxt] + (rbg + er) * HDIM + j0 + ej, hn + cw);
                if (t == LSEQ - 1)
                    out[(rbg + er) * HDIM + j0 + ej] = hn;
            }
            // no extra barrier: Bf rewrite next half is after sync(1) there;
            // Gsm2 rewrite is after that sync too; tokb slots parity-disjoint.
        }
    }
}

// ---------------------------------------------------------------------------
// launcher
// ---------------------------------------------------------------------------
extern "C" void kernel_launch(void* const* d_in, const int* in_sizes, int n_in,
                              void* d_out, int out_size)
{
    (void)in_sizes; (void)n_in; (void)out_size;
    const void*  X   = d_in[0];
    const float* E   = (const float*)d_in[1];
    const float* Ww  = (const float*)d_in[2];
    const float* Wb  = (const float*)d_in[3];
    float*       out = (float*)d_out;

    split_kernel<<<8192, 256>>>(E, Ww);
    table_kernel<<<dim3(VOC / 64, G3 / 64), 256>>>(Wb);
    lstm_kernel<<<64, NT>>>(X, Ww, out);
}

// round 14
// speedup vs baseline: 1.0701x; 1.0701x over previous
#include <cuda_runtime.h>
#include <cuda_bf16.h>
#include <cstdint>

// ---------------------------------------------------------------------------
// SimpleLSTM on GB300 (plain sm_103 PTX) — round 14:
//   lstm: r11 HMMA recurrence with M-permutation m = jj*4 + gate (M=128,
//   gate3 = zero pad). Warp w owns all 3 gates of hidden cols [4w,4w+4):
//   epilogue is warp-local (private staging + syncwarp), C lives in a
//   register, ONE block barrier per step, Bf double-buffered.
//   H exchange: tagged data, ALL FOUR words of each 16B chunk carry the tag
//   (stores are now per-word).
//   table: bf16-split HMMA GEMM + split_kernel (r11, unchanged).
// ---------------------------------------------------------------------------

#define NB    128
#define LSEQ  2048
#define HDIM  256
#define EMB   256
#define VOC   32000
#define G3    768
#define NT    256

__device__ float    g_T[VOC * G3];          // token-gate table (~98.3 MB)
__device__ float    g_Hbuf[2][NB * HDIM];   // H double buffer (tagged values)
__device__ uint32_t g_EhG[VOC * 128];       // E hi split, bf16x2 words
__device__ uint32_t g_ElG[VOC * 128];       // E lo split
__device__ uint32_t g_WhG[G3 * 128];        // W_x hi split (live gate rows)
__device__ uint32_t g_WlG[G3 * 128];        // W_x lo split

// ---------------------------------------------------------------------------
// helpers
// ---------------------------------------------------------------------------
__device__ __forceinline__ float4 ldv4_volatile(const float* p)
{
    float4 v;
    asm volatile("ld.volatile.global.v4.f32 {%0, %1, %2, %3}, [%4];"
                 : "=f"(v.x), "=f"(v.y), "=f"(v.z), "=f"(v.w) : "l"(p)
                 : "memory");
    return v;
}

__device__ __forceinline__ float sig_fast(float x)
{
    return __fdividef(1.0f, 1.0f + __expf(-x));
}

__device__ __forceinline__ float tanh_fast(float x)
{
    return __fdividef(2.0f, 1.0f + __expf(-2.0f * x)) - 1.0f;
}

// split a float2 (consecutive k pair) into bf16x2 hi and lo b32 values.
__device__ __forceinline__ void split2(float2 f, uint32_t& hi, uint32_t& lo)
{
    __nv_bfloat16 h0 = __float2bfloat16_rn(f.x);
    __nv_bfloat16 h1 = __float2bfloat16_rn(f.y);
    __nv_bfloat16 l0 = __float2bfloat16_rn(f.x - __bfloat162float(h0));
    __nv_bfloat16 l1 = __float2bfloat16_rn(f.y - __bfloat162float(h1));
    __nv_bfloat162 ph = __halves2bfloat162(h0, h1);
    __nv_bfloat162 pl = __halves2bfloat162(l0, l1);
    hi = *(uint32_t*)&ph;
    lo = *(uint32_t*)&pl;
}

__device__ __forceinline__ void mma16816(float& c0, float& c1, float& c2, float& c3,
                                         uint32_t a0, uint32_t a1, uint32_t a2, uint32_t a3,
                                         uint32_t b0, uint32_t b1)
{
    asm volatile(
        "mma.sync.aligned.m16n8k16.row.col.f32.bf16.bf16.f32 "
        "{%0,%1,%2,%3}, {%4,%5,%6,%7}, {%8,%9}, {%0,%1,%2,%3};"
        : "+f"(c0), "+f"(c1), "+f"(c2), "+f"(c3)
        : "r"(a0), "r"(a1), "r"(a2), "r"(a3), "r"(b0), "r"(b1));
}

__device__ __forceinline__ int grow_of(int g)   // live-gate row -> W row
{
    int gate = g >> 8, jj = g & 255;
    return (gate == 0 ? 0 : (gate == 1 ? 512 : 768)) + jj;
}

// ---------------------------------------------------------------------------
// Kernel 0: split E and W_x (input half, live gate rows) into bf16 hi/lo.
// ---------------------------------------------------------------------------
__global__ void split_kernel(const float* __restrict__ E,
                             const float* __restrict__ Ww)
{
    int idx = blockIdx.x * 256 + threadIdx.x;
    uint32_t h0, l0, h1, l1;
    if (idx < VOC * 64) {
        int row = idx >> 6, f4 = idx & 63;
        float4 e = *(const float4*)(E + row * EMB + f4 * 4);
        split2(make_float2(e.x, e.y), h0, l0);
        split2(make_float2(e.z, e.w), h1, l1);
        *(uint2*)&g_EhG[row * 128 + f4 * 2] = make_uint2(h0, h1);
        *(uint2*)&g_ElG[row * 128 + f4 * 2] = make_uint2(l0, l1);
    } else {
        int widx = idx - VOC * 64;
        int row = widx >> 6, f4 = widx & 63;      // row = live gate idx 0..767
        int grow = grow_of(row);
        float4 w = *(const float4*)(Ww + grow * 512 + 256 + f4 * 4);
        split2(make_float2(w.x, w.y), h0, l0);
        split2(make_float2(w.z, w.w), h1, l1);
        *(uint2*)&g_WhG[row * 128 + f4 * 2] = make_uint2(h0, h1);
        *(uint2*)&g_WlG[row * 128 + f4 * 2] = make_uint2(l0, l1);
    }
}

// ---------------------------------------------------------------------------
// Kernel 1: token table GEMM via HMMA (M=32000, N=768, K=256), 64x64 tiles.
// ---------------------------------------------------------------------------
__global__ void __launch_bounds__(256)
table_kernel(const float* __restrict__ Wb)
{
    __shared__ uint32_t Eh[64 * 36], El[64 * 36];
    __shared__ uint32_t Wh[64 * 36], Wl[64 * 36];

    const int tid  = threadIdx.x;
    const int v0   = blockIdx.x * 64;
    const int g0   = blockIdx.y * 64;
    const int wid  = tid >> 5, lane = tid & 31;
    const int gid  = lane >> 2, tig = lane & 3;
    const int m0   = (wid & 3) * 16;
    const int n0   = (wid >> 2) * 32;

    float acc[4][4];
#pragma unroll
    for (int i = 0; i < 4; i++)
#pragma unroll
        for (int j = 0; j < 4; j++) acc[i][j] = 0.0f;

    for (int c = 0; c < 4; c++) {          // K chunk of 64
#pragma unroll
        for (int it = 0; it < 8; it++) {
            int idx = tid + it * 256;       // 0..2047
            int buf = idx >> 9, rem = idx & 511;
            int row = rem >> 3, w4 = rem & 7;
            const uint32_t* src;
            uint32_t* dst;
            if (buf == 0)      { src = &g_EhG[(v0 + row) * 128]; dst = Eh; }
            else if (buf == 1) { src = &g_ElG[(v0 + row) * 128]; dst = El; }
            else if (buf == 2) { src = &g_WhG[(g0 + row) * 128]; dst = Wh; }
            else               { src = &g_WlG[(g0 + row) * 128]; dst = Wl; }
            uint4 v = *(const uint4*)(src + c * 32 + w4 * 4);
            *(uint4*)(dst + row * 36 + w4 * 4) = v;
        }
        __syncthreads();

#pragma unroll
        for (int ktL = 0; ktL < 4; ktL++) {
            int kw = ktL * 8 + tig;
            uint32_t ah0 = Eh[(m0 + gid) * 36 + kw];
            uint32_t ah1 = Eh[(m0 + gid + 8) * 36 + kw];
            uint32_t ah2 = Eh[(m0 + gid) * 36 + kw + 4];
            uint32_t ah3 = Eh[(m0 + gid + 8) * 36 + kw + 4];
            uint32_t al0 = El[(m0 + gid) * 36 + kw];
            uint32_t al1 = El[(m0 + gid + 8) * 36 + kw];
            uint32_t al2 = El[(m0 + gid) * 36 + kw + 4];
            uint32_t al3 = El[(m0 + gid + 8) * 36 + kw + 4];
#pragma unroll
            for (int nn = 0; nn < 4; nn++) {
                int wr = (n0 + nn * 8 + gid) * 36 + kw;
                uint32_t bh0 = Wh[wr], bh1 = Wh[wr + 4];
                uint32_t bl0 = Wl[wr], bl1 = Wl[wr + 4];
                mma16816(acc[nn][0], acc[nn][1], acc[nn][2], acc[nn][3],
                         ah0, ah1, ah2, ah3, bh0, bh1);
                mma16816(acc[nn][0], acc[nn][1], acc[nn][2], acc[nn][3],
                         ah0, ah1, ah2, ah3, bl0, bl1);
                mma16816(acc[nn][0], acc[nn][1], acc[nn][2], acc[nn][3],
                         al0, al1, al2, al3, bh0, bh1);
            }
        }
        __syncthreads();
    }

#pragma unroll
    for (int nn = 0; nn < 4; nn++) {
        int g  = g0 + n0 + nn * 8 + tig * 2;
        float b0 = Wb[grow_of(g)];
        float b1 = Wb[grow_of(g + 1)];
        int vA = v0 + m0 + gid, vB = vA + 8;
        *(float2*)&g_T[vA * G3 + g] = make_float2(acc[nn][0] + b0, acc[nn][1] + b1);
        *(float2*)&g_T[vB * G3 + g] = make_float2(acc[nn][2] + b0, acc[nn][3] + b1);
    }
}

// ---------------------------------------------------------------------------
// Kernel 2: persistent recurrence, M-permuted HMMA, one barrier per step.
//   m = jj*4 + gate (jj = col within 32-tile, gate 0..2, 3 = zero pad).
//   Warp w: MMA rows m in [16w, 16w+16) = cols jj in [4w, 4w+4), all gates.
// ---------------------------------------------------------------------------

#define KTW   132           // words per k-tile slot (128 + 4 pad)
#define BFH   (16 * KTW)    // words per Bf buffer

__global__ void __launch_bounds__(NT, 1)
lstm_kernel(const void* __restrict__ Xraw,
            const float* __restrict__ Ww,
            float* __restrict__ out)
{
    __shared__ uint32_t Bf[2 * BFH];     // double-buffered B fragments
    __shared__ float    Wst[8 * 144];    // per-warp staging [m_local][n] str 9
    __shared__ int      tokb[2][8];

    const int tid  = threadIdx.x;
    const int wid  = tid >> 5;
    const int lane = tid & 31;
    const int bt   = blockIdx.x >> 3;
    const int ct   = blockIdx.x & 7;
    const int rb   = bt * 8;
    const int j0   = ct * 32;

    const int gid = lane >> 2;      // mma group id
    const int tig = lane & 3;       // mma thread-in-group

    // --- int64 vs int32 token buffer detection ----------------------------
    const int* Xi = (const int*)Xraw;
    bool is64 = true;
#pragma unroll
    for (int i = 0; i < 16; i++)
        if (Xi[2 * i + 1] != 0) is64 = false;
    const long long* Xl = (const long long*)Xraw;

    // --- init ----------------------------------------------------------------
    for (int i = tid; i < 2 * BFH; i += NT) Bf[i] = 0u;
    if (tid < 8)
        tokb[0][tid] = is64 ? (int)Xl[(rb + tid) * LSEQ] : Xi[(rb + tid) * LSEQ];

    // --- build W A-fragments (all 8 warps), permuted m = jj*4 + gate ---------
    //   rows: m_a = 16w + gid  (jj_a = 4w + (gid>>2), gate = gid&3)
    //         m_b = m_a + 8    (jj_b = jj_a + 2,      same gate)
    uint32_t A1[16][4], A2[16][4];
    {
        const int gate = gid & 3;
        const bool dead = (gate == 3);
        const int jjA = 4 * wid + (gid >> 2);
        const int jjB = jjA + 2;
        const int gb  = (gate == 0 ? 0 : (gate == 1 ? 512 : 768));
        const int growA = gb + j0 + jjA;
        const int growB = gb + j0 + jjB;
#pragma unroll
        for (int kt = 0; kt < 16; kt++) {
            if (dead) {
                A1[kt][0] = A1[kt][1] = A1[kt][2] = A1[kt][3] = 0u;
                A2[kt][0] = A2[kt][1] = A2[kt][2] = A2[kt][3] = 0u;
            } else {
                int k = kt * 16 + tig * 2;
                float2 f;
                f = __ldg((const float2*)(Ww + growA * 512 + k));
                split2(f, A1[kt][0], A2[kt][0]);
                f = __ldg((const float2*)(Ww + growB * 512 + k));
                split2(f, A1[kt][1], A2[kt][1]);
                f = __ldg((const float2*)(Ww + growA * 512 + k + 8));
                split2(f, A1[kt][2], A2[kt][2]);
                f = __ldg((const float2*)(Ww + growB * 512 + k + 8));
                split2(f, A1[kt][3], A2[kt][3]);
            }
        }
    }
    __syncthreads();

    // --- fill mapping (all 8 warps; producer rank = wid) --------------------
    const int kq = wid;
    const int fq = lane & 7;            // k-quad within slice
    const int r0 = lane >> 3;           // batch rows 0..3 (v0)
    const int r1 = r0 + 4;              // batch rows 4..7 (v1)
    const int fkt  = kq * 2 + (fq >> 2);
    const int freg = (fq >> 1) & 1;
    const int ftig = (fq & 1) * 2;
    uint2* B2 = (uint2*)Bf;
    const int u0a = fkt * (KTW / 2) + (r0 * 4 + ftig) * 2 + freg;
    const int u0b = fkt * (KTW / 2) + (r0 * 4 + ftig + 1) * 2 + freg;
    const int u1a = fkt * (KTW / 2) + (r1 * 4 + ftig) * 2 + freg;
    const int u1b = fkt * (KTW / 2) + (r1 * 4 + ftig + 1) * 2 + freg;
    const int off0 = r0 * HDIM + kq * 32 + fq * 4;   // + rb*HDIM at use
    const int off1 = r1 * HDIM + kq * 32 + fq * 4;

    // epilogue mapping: lane -> (r_e, jj_e); output col = j0 + 4*wid + jj_e
    const int jj_e = lane >> 3;
    const int r_e  = lane & 7;
    const int jcol = j0 + 4 * wid + jj_e;
    float* ws = &Wst[wid * 144];

    float cReg = 0.0f;                   // C state (one element per lane)

    for (int t = 0; t < LSEQ; t++) {
        const int cur = t & 1, nxt = cur ^ 1;
        const int bsel  = (t & 1) * (BFH / 2);   // uint2 offset for fill
        const int bselW = (t & 1) * BFH;         // word offset for MMA

        // ---- Gx prefetch (token-determined; overlaps the poll) ------------
        const float* Tr = g_T + (long long)tokb[cur][r_e] * G3 + jcol;
        float gxF = __ldg(Tr);
        float gxO = __ldg(Tr + 256);
        float gxH = __ldg(Tr + 512);

        if (tid < 8 && t + 1 < LSEQ)
            tokb[nxt][tid] = is64 ? (int)Xl[(rb + tid) * LSEQ + t + 1]
                                  : Xi[(rb + tid) * LSEQ + t + 1];

        // ---- fill: poll tagged H slice (all 4 words tagged), STS Bf --------
        if (t > 0) {
            const float cr = 4.0f + 8.0f * (float)(((t - 1) >> 1) & 3);
            const float* hb = g_Hbuf[cur];
            const float* p0 = hb + rb * HDIM + off0;
            const float* p1 = hb + rb * HDIM + off1;
            float4 v0, v1;
            bool d0 = false, d1 = false;
            do {
                if (!d0) {
                    v0 = ldv4_volatile(p0);
                    d0 = fabsf(v0.x - cr) < 2.0f && fabsf(v0.y - cr) < 2.0f &&
                         fabsf(v0.z - cr) < 2.0f && fabsf(v0.w - cr) < 2.0f;
                }
                if (!d1) {
                    v1 = ldv4_volatile(p1);
                    d1 = fabsf(v1.x - cr) < 2.0f && fabsf(v1.y - cr) < 2.0f &&
                         fabsf(v1.z - cr) < 2.0f && fabsf(v1.w - cr) < 2.0f;
                }
            } while (!(d0 && d1));
            v0.x -= cr; v0.y -= cr; v0.z -= cr; v0.w -= cr;
            v1.x -= cr; v1.y -= cr; v1.z -= cr; v1.w -= cr;
            uint32_t h0, l0, h1, l1;
            split2(make_float2(v0.x, v0.y), h0, l0);
            split2(make_float2(v0.z, v0.w), h1, l1);
            B2[bsel + u0a] = make_uint2(h0, l0);
            B2[bsel + u0b] = make_uint2(h1, l1);
            split2(make_float2(v1.x, v1.y), h0, l0);
            split2(make_float2(v1.z, v1.w), h1, l1);
            B2[bsel + u1a] = make_uint2(h0, l0);
            B2[bsel + u1b] = make_uint2(h1, l1);
        }
        __syncthreads();   // the ONLY block barrier per step: Bf[t&1] ready

        // ---- HMMA: all 8 warps, 16 k-tiles x 3 split terms ------------------
        float cA0 = 0.f, cA1 = 0.f, cA2 = 0.f, cA3 = 0.f;
        float cB0 = 0.f, cB1 = 0.f, cB2 = 0.f, cB3 = 0.f;
        float cC0 = 0.f, cC1 = 0.f, cC2 = 0.f, cC3 = 0.f;
#pragma unroll
        for (int kt = 0; kt < 16; kt++) {
            uint4 b = *(const uint4*)&Bf[bselW + kt * KTW + lane * 4];
            // words: x=b1(hi,k-lo), y=b2(lo,k-lo), z=b1(hi,k-hi), w=b2(lo,k-hi)
            mma16816(cA0, cA1, cA2, cA3,
                     A1[kt][0], A1[kt][1], A1[kt][2], A1[kt][3], b.x, b.z);
            mma16816(cB0, cB1, cB2, cB3,
                     A1[kt][0], A1[kt][1], A1[kt][2], A1[kt][3], b.y, b.w);
            mma16816(cC0, cC1, cC2, cC3,
                     A2[kt][0], A2[kt][1], A2[kt][2], A2[kt][3], b.x, b.z);
        }

        // ---- warp-local staging: [m_local][n] stride 9 ----------------------
        ws[gid * 9 + 2 * tig]           = cA0 + cB0 + cC0;
        ws[gid * 9 + 2 * tig + 1]       = cA1 + cB1 + cC1;
        ws[(gid + 8) * 9 + 2 * tig]     = cA2 + cB2 + cC2;
        ws[(gid + 8) * 9 + 2 * tig + 1] = cA3 + cB3 + cC3;
        __syncwarp();

        // ---- epilogue: gates, C (register), H_new (per-word tagged store) ---
        {
            const float cw = 4.0f + 8.0f * (float)((t >> 1) & 3);
            float gF = gxF + ws[(4 * jj_e + 0) * 9 + r_e];
            float gO = gxO + ws[(4 * jj_e + 1) * 9 + r_e];
            float gH = gxH + ws[(4 * jj_e + 2) * 9 + r_e];
            float F  = sig_fast(gF);
            float O  = sig_fast(gO);
            float Ht = tanh_fast(gH);
            cReg = F * cReg + O * Ht;            // faithful: uses O, not I
            float hn = O * tanh_fast(cReg);
            __stcg(g_Hbuf[nxt] + (rb + r_e) * HDIM + jcol, hn + cw);
            if (t == LSEQ - 1)
                out[(rb + r_e) * HDIM + jcol] = hn;
        }
        __syncwarp();   // ws stable before next step's staging writes
        // Bf: double-buffered; overwrite of buffer b at fill t+2 is safe
        // (sync at t+1 implies all warps completed MMA t).
    }
}

// ---------------------------------------------------------------------------
// launcher
// ---------------------------------------------------------------------------
extern "C" void kernel_launch(void* const* d_in, const int* in_sizes, int n_in,
                              void* d_out, int out_size)
{
    (void)in_sizes; (void)n_in; (void)out_size;
    const void*  X   = d_in[0];
    const float* E   = (const float*)d_in[1];
    const float* Ww  = (const float*)d_in[2];
    const float* Wb  = (const float*)d_in[3];
    float*       out = (float*)d_out;

    split_kernel<<<8192, 256>>>(E, Ww);
    table_kernel<<<dim3(VOC / 64, G3 / 64), 256>>>(Wb);
    lstm_kernel<<<128, NT>>>(X, Ww, out);
}

// round 15
// speedup vs baseline: 1.1119x; 1.0391x over previous
#include <cuda_runtime.h>
#include <cuda_bf16.h>
#include <cstdint>

// ---------------------------------------------------------------------------
// SimpleLSTM on GB300 (plain sm_103 PTX) — round 15:
//   lstm: M-permuted HMMA recurrence (m = jj*4 + gate, M=128, gate3 = pad).
//   Warp w owns all 3 gates of hidden cols [4w, 4w+4): epilogue is warp-local
//   (C in a register), ONE block barrier per step, Bf double-buffered.
//   H stores: warp gathers its 32 tagged h values in SMEM and emits 8
//   STG.128 (16B chunks atomic) -> consumer polls word0-only tags.
//   table: bf16-split HMMA GEMM + split_kernel (r11, unchanged).
// ---------------------------------------------------------------------------

#define NB    128
#define LSEQ  2048
#define HDIM  256
#define EMB   256
#define VOC   32000
#define G3    768
#define NT    256

__device__ float    g_T[VOC * G3];          // token-gate table (~98.3 MB)
__device__ float    g_Hbuf[2][NB * HDIM];   // H double buffer (tagged values)
__device__ uint32_t g_EhG[VOC * 128];       // E hi split, bf16x2 words
__device__ uint32_t g_ElG[VOC * 128];       // E lo split
__device__ uint32_t g_WhG[G3 * 128];        // W_x hi split (live gate rows)
__device__ uint32_t g_WlG[G3 * 128];        // W_x lo split

// ---------------------------------------------------------------------------
// helpers
// ---------------------------------------------------------------------------
__device__ __forceinline__ float4 ldv4_volatile(const float* p)
{
    float4 v;
    asm volatile("ld.volatile.global.v4.f32 {%0, %1, %2, %3}, [%4];"
                 : "=f"(v.x), "=f"(v.y), "=f"(v.z), "=f"(v.w) : "l"(p)
                 : "memory");
    return v;
}

__device__ __forceinline__ float sig_fast(float x)
{
    return __fdividef(1.0f, 1.0f + __expf(-x));
}

__device__ __forceinline__ float tanh_fast(float x)
{
    return __fdividef(2.0f, 1.0f + __expf(-2.0f * x)) - 1.0f;
}

// split a float2 (consecutive k pair) into bf16x2 hi and lo b32 values.
__device__ __forceinline__ void split2(float2 f, uint32_t& hi, uint32_t& lo)
{
    __nv_bfloat16 h0 = __float2bfloat16_rn(f.x);
    __nv_bfloat16 h1 = __float2bfloat16_rn(f.y);
    __nv_bfloat16 l0 = __float2bfloat16_rn(f.x - __bfloat162float(h0));
    __nv_bfloat16 l1 = __float2bfloat16_rn(f.y - __bfloat162float(h1));
    __nv_bfloat162 ph = __halves2bfloat162(h0, h1);
    __nv_bfloat162 pl = __halves2bfloat162(l0, l1);
    hi = *(uint32_t*)&ph;
    lo = *(uint32_t*)&pl;
}

__device__ __forceinline__ void mma16816(float& c0, float& c1, float& c2, float& c3,
                                         uint32_t a0, uint32_t a1, uint32_t a2, uint32_t a3,
                                         uint32_t b0, uint32_t b1)
{
    asm volatile(
        "mma.sync.aligned.m16n8k16.row.col.f32.bf16.bf16.f32 "
        "{%0,%1,%2,%3}, {%4,%5,%6,%7}, {%8,%9}, {%0,%1,%2,%3};"
        : "+f"(c0), "+f"(c1), "+f"(c2), "+f"(c3)
        : "r"(a0), "r"(a1), "r"(a2), "r"(a3), "r"(b0), "r"(b1));
}

__device__ __forceinline__ int grow_of(int g)   // live-gate row -> W row
{
    int gate = g >> 8, jj = g & 255;
    return (gate == 0 ? 0 : (gate == 1 ? 512 : 768)) + jj;
}

// ---------------------------------------------------------------------------
// Kernel 0: split E and W_x (input half, live gate rows) into bf16 hi/lo.
// ---------------------------------------------------------------------------
__global__ void split_kernel(const float* __restrict__ E,
                             const float* __restrict__ Ww)
{
    int idx = blockIdx.x * 256 + threadIdx.x;
    uint32_t h0, l0, h1, l1;
    if (idx < VOC * 64) {
        int row = idx >> 6, f4 = idx & 63;
        float4 e = *(const float4*)(E + row * EMB + f4 * 4);
        split2(make_float2(e.x, e.y), h0, l0);
        split2(make_float2(e.z, e.w), h1, l1);
        *(uint2*)&g_EhG[row * 128 + f4 * 2] = make_uint2(h0, h1);
        *(uint2*)&g_ElG[row * 128 + f4 * 2] = make_uint2(l0, l1);
    } else {
        int widx = idx - VOC * 64;
        int row = widx >> 6, f4 = widx & 63;      // row = live gate idx 0..767
        int grow = grow_of(row);
        float4 w = *(const float4*)(Ww + grow * 512 + 256 + f4 * 4);
        split2(make_float2(w.x, w.y), h0, l0);
        split2(make_float2(w.z, w.w), h1, l1);
        *(uint2*)&g_WhG[row * 128 + f4 * 2] = make_uint2(h0, h1);
        *(uint2*)&g_WlG[row * 128 + f4 * 2] = make_uint2(l0, l1);
    }
}

// ---------------------------------------------------------------------------
// Kernel 1: token table GEMM via HMMA (M=32000, N=768, K=256), 64x64 tiles.
// ---------------------------------------------------------------------------
__global__ void __launch_bounds__(256)
table_kernel(const float* __restrict__ Wb)
{
    __shared__ uint32_t Eh[64 * 36], El[64 * 36];
    __shared__ uint32_t Wh[64 * 36], Wl[64 * 36];

    const int tid  = threadIdx.x;
    const int v0   = blockIdx.x * 64;
    const int g0   = blockIdx.y * 64;
    const int wid  = tid >> 5, lane = tid & 31;
    const int gid  = lane >> 2, tig = lane & 3;
    const int m0   = (wid & 3) * 16;
    const int n0   = (wid >> 2) * 32;

    float acc[4][4];
#pragma unroll
    for (int i = 0; i < 4; i++)
#pragma unroll
        for (int j = 0; j < 4; j++) acc[i][j] = 0.0f;

    for (int c = 0; c < 4; c++) {          // K chunk of 64
#pragma unroll
        for (int it = 0; it < 8; it++) {
            int idx = tid + it * 256;       // 0..2047
            int buf = idx >> 9, rem = idx & 511;
            int row = rem >> 3, w4 = rem & 7;
            const uint32_t* src;
            uint32_t* dst;
            if (buf == 0)      { src = &g_EhG[(v0 + row) * 128]; dst = Eh; }
            else if (buf == 1) { src = &g_ElG[(v0 + row) * 128]; dst = El; }
            else if (buf == 2) { src = &g_WhG[(g0 + row) * 128]; dst = Wh; }
            else               { src = &g_WlG[(g0 + row) * 128]; dst = Wl; }
            uint4 v = *(const uint4*)(src + c * 32 + w4 * 4);
            *(uint4*)(dst + row * 36 + w4 * 4) = v;
        }
        __syncthreads();

#pragma unroll
        for (int ktL = 0; ktL < 4; ktL++) {
            int kw = ktL * 8 + tig;
            uint32_t ah0 = Eh[(m0 + gid) * 36 + kw];
            uint32_t ah1 = Eh[(m0 + gid + 8) * 36 + kw];
            uint32_t ah2 = Eh[(m0 + gid) * 36 + kw + 4];
            uint32_t ah3 = Eh[(m0 + gid + 8) * 36 + kw + 4];
            uint32_t al0 = El[(m0 + gid) * 36 + kw];
            uint32_t al1 = El[(m0 + gid + 8) * 36 + kw];
            uint32_t al2 = El[(m0 + gid) * 36 + kw + 4];
            uint32_t al3 = El[(m0 + gid + 8) * 36 + kw + 4];
#pragma unroll
            for (int nn = 0; nn < 4; nn++) {
                int wr = (n0 + nn * 8 + gid) * 36 + kw;
                uint32_t bh0 = Wh[wr], bh1 = Wh[wr + 4];
                uint32_t bl0 = Wl[wr], bl1 = Wl[wr + 4];
                mma16816(acc[nn][0], acc[nn][1], acc[nn][2], acc[nn][3],
                         ah0, ah1, ah2, ah3, bh0, bh1);
                mma16816(acc[nn][0], acc[nn][1], acc[nn][2], acc[nn][3],
                         ah0, ah1, ah2, ah3, bl0, bl1);
                mma16816(acc[nn][0], acc[nn][1], acc[nn][2], acc[nn][3],
                         al0, al1, al2, al3, bh0, bh1);
            }
        }
        __syncthreads();
    }

#pragma unroll
    for (int nn = 0; nn < 4; nn++) {
        int g  = g0 + n0 + nn * 8 + tig * 2;
        float b0 = Wb[grow_of(g)];
        float b1 = Wb[grow_of(g + 1)];
        int vA = v0 + m0 + gid, vB = vA + 8;
        *(float2*)&g_T[vA * G3 + g] = make_float2(acc[nn][0] + b0, acc[nn][1] + b1);
        *(float2*)&g_T[vB * G3 + g] = make_float2(acc[nn][2] + b0, acc[nn][3] + b1);
    }
}

// ---------------------------------------------------------------------------
// Kernel 2: persistent recurrence, M-permuted HMMA, one barrier per step,
//           gathered STG.128 tagged H stores.
// ---------------------------------------------------------------------------

#define KTW   132           // words per k-tile slot (128 + 4 pad)
#define BFH   (16 * KTW)    // words per Bf buffer

__global__ void __launch_bounds__(NT, 1)
lstm_kernel(const void* __restrict__ Xraw,
            const float* __restrict__ Ww,
            float* __restrict__ out)
{
    __shared__ uint32_t Bf[2 * BFH];        // double-buffered B fragments
    __shared__ float    Wst[8 * 144];       // per-warp G staging [m_local][n] str 9
    __shared__ __align__(16) float Hout[8 * 32];  // per-warp gathered tagged h
    __shared__ int      tokb[2][8];

    const int tid  = threadIdx.x;
    const int wid  = tid >> 5;
    const int lane = tid & 31;
    const int bt   = blockIdx.x >> 3;
    const int ct   = blockIdx.x & 7;
    const int rb   = bt * 8;
    const int j0   = ct * 32;

    const int gid = lane >> 2;      // mma group id
    const int tig = lane & 3;       // mma thread-in-group

    // --- int64 vs int32 token buffer detection ----------------------------
    const int* Xi = (const int*)Xraw;
    bool is64 = true;
#pragma unroll
    for (int i = 0; i < 16; i++)
        if (Xi[2 * i + 1] != 0) is64 = false;
    const long long* Xl = (const long long*)Xraw;

    // --- init ----------------------------------------------------------------
    for (int i = tid; i < 2 * BFH; i += NT) Bf[i] = 0u;
    if (tid < 8)
        tokb[0][tid] = is64 ? (int)Xl[(rb + tid) * LSEQ] : Xi[(rb + tid) * LSEQ];

    // --- build W A-fragments (all 8 warps), permuted m = jj*4 + gate ---------
    uint32_t A1[16][4], A2[16][4];
    {
        const int gate = gid & 3;
        const bool dead = (gate == 3);
        const int jjA = 4 * wid + (gid >> 2);
        const int jjB = jjA + 2;
        const int gb  = (gate == 0 ? 0 : (gate == 1 ? 512 : 768));
        const int growA = gb + j0 + jjA;
        const int growB = gb + j0 + jjB;
#pragma unroll
        for (int kt = 0; kt < 16; kt++) {
            if (dead) {
                A1[kt][0] = A1[kt][1] = A1[kt][2] = A1[kt][3] = 0u;
                A2[kt][0] = A2[kt][1] = A2[kt][2] = A2[kt][3] = 0u;
            } else {
                int k = kt * 16 + tig * 2;
                float2 f;
                f = __ldg((const float2*)(Ww + growA * 512 + k));
                split2(f, A1[kt][0], A2[kt][0]);
                f = __ldg((const float2*)(Ww + growB * 512 + k));
                split2(f, A1[kt][1], A2[kt][1]);
                f = __ldg((const float2*)(Ww + growA * 512 + k + 8));
                split2(f, A1[kt][2], A2[kt][2]);
                f = __ldg((const float2*)(Ww + growB * 512 + k + 8));
                split2(f, A1[kt][3], A2[kt][3]);
            }
        }
    }
    __syncthreads();

    // --- fill mapping (all 8 warps; producer rank = wid) --------------------
    const int kq = wid;
    const int fq = lane & 7;            // k-quad within slice
    const int r0 = lane >> 3;           // batch rows 0..3 (v0)
    const int r1 = r0 + 4;              // batch rows 4..7 (v1)
    const int fkt  = kq * 2 + (fq >> 2);
    const int freg = (fq >> 1) & 1;
    const int ftig = (fq & 1) * 2;
    uint2* B2 = (uint2*)Bf;
    const int u0a = fkt * (KTW / 2) + (r0 * 4 + ftig) * 2 + freg;
    const int u0b = fkt * (KTW / 2) + (r0 * 4 + ftig + 1) * 2 + freg;
    const int u1a = fkt * (KTW / 2) + (r1 * 4 + ftig) * 2 + freg;
    const int u1b = fkt * (KTW / 2) + (r1 * 4 + ftig + 1) * 2 + freg;
    const int off0 = r0 * HDIM + kq * 32 + fq * 4;   // + rb*HDIM at use
    const int off1 = r1 * HDIM + kq * 32 + fq * 4;

    // epilogue mapping: lane -> (r_e, jj_e); output col = j0 + 4*wid + jj_e
    const int jj_e = lane >> 3;
    const int r_e  = lane & 7;
    const int jcol = j0 + 4 * wid + jj_e;
    float* ws = &Wst[wid * 144];
    float* ho = &Hout[wid * 32];

    float cReg = 0.0f;                   // C state (one element per lane)

    for (int t = 0; t < LSEQ; t++) {
        const int cur = t & 1, nxt = cur ^ 1;
        const int bsel  = (t & 1) * (BFH / 2);   // uint2 offset for fill
        const int bselW = (t & 1) * BFH;         // word offset for MMA

        // ---- Gx prefetch (token-determined; overlaps the poll) ------------
        const float* Tr = g_T + (long long)tokb[cur][r_e] * G3 + jcol;
        float gxF = __ldg(Tr);
        float gxO = __ldg(Tr + 256);
        float gxH = __ldg(Tr + 512);

        if (tid < 8 && t + 1 < LSEQ)
            tokb[nxt][tid] = is64 ? (int)Xl[(rb + tid) * LSEQ + t + 1]
                                  : Xi[(rb + tid) * LSEQ + t + 1];

        // ---- fill: poll tagged H slice (word0 tag), STS Bf ------------------
        if (t > 0) {
            const float cr = 4.0f + 8.0f * (float)(((t - 1) >> 1) & 3);
            const float* hb = g_Hbuf[cur];
            const float* p0 = hb + rb * HDIM + off0;
            const float* p1 = hb + rb * HDIM + off1;
            float4 v0, v1;
            bool d0 = false, d1 = false;
            do {
                if (!d0) { v0 = ldv4_volatile(p0); d0 = fabsf(v0.x - cr) < 2.0f; }
                if (!d1) { v1 = ldv4_volatile(p1); d1 = fabsf(v1.x - cr) < 2.0f; }
            } while (!(d0 && d1));
            v0.x -= cr; v0.y -= cr; v0.z -= cr; v0.w -= cr;
            v1.x -= cr; v1.y -= cr; v1.z -= cr; v1.w -= cr;
            uint32_t h0, l0, h1, l1;
            split2(make_float2(v0.x, v0.y), h0, l0);
            split2(make_float2(v0.z, v0.w), h1, l1);
            B2[bsel + u0a] = make_uint2(h0, l0);
            B2[bsel + u0b] = make_uint2(h1, l1);
            split2(make_float2(v1.x, v1.y), h0, l0);
            split2(make_float2(v1.z, v1.w), h1, l1);
            B2[bsel + u1a] = make_uint2(h0, l0);
            B2[bsel + u1b] = make_uint2(h1, l1);
        }
        __syncthreads();   // the ONLY block barrier per step: Bf[t&1] ready

        // ---- HMMA: all 8 warps, 16 k-tiles x 3 split terms -------------------
        float cA0 = 0.f, cA1 = 0.f, cA2 = 0.f, cA3 = 0.f;
        float cB0 = 0.f, cB1 = 0.f, cB2 = 0.f, cB3 = 0.f;
        float cC0 = 0.f, cC1 = 0.f, cC2 = 0.f, cC3 = 0.f;
#pragma unroll
        for (int kt = 0; kt < 16; kt++) {
            uint4 b = *(const uint4*)&Bf[bselW + kt * KTW + lane * 4];
            mma16816(cA0, cA1, cA2, cA3,
                     A1[kt][0], A1[kt][1], A1[kt][2], A1[kt][3], b.x, b.z);
            mma16816(cB0, cB1, cB2, cB3,
                     A1[kt][0], A1[kt][1], A1[kt][2], A1[kt][3], b.y, b.w);
            mma16816(cC0, cC1, cC2, cC3,
                     A2[kt][0], A2[kt][1], A2[kt][2], A2[kt][3], b.x, b.z);
        }

        // ---- warp-local staging: [m_local][n] stride 9 -----------------------
        ws[gid * 9 + 2 * tig]           = cA0 + cB0 + cC0;
        ws[gid * 9 + 2 * tig + 1]       = cA1 + cB1 + cC1;
        ws[(gid + 8) * 9 + 2 * tig]     = cA2 + cB2 + cC2;
        ws[(gid + 8) * 9 + 2 * tig + 1] = cA3 + cB3 + cC3;
        __syncwarp();

        // ---- epilogue: gates, C (register), gather tagged h ------------------
        float hn;
        {
            const float cw = 4.0f + 8.0f * (float)((t >> 1) & 3);
            float gF = gxF + ws[(4 * jj_e + 0) * 9 + r_e];
            float gO = gxO + ws[(4 * jj_e + 1) * 9 + r_e];
            float gH = gxH + ws[(4 * jj_e + 2) * 9 + r_e];
            float F  = sig_fast(gF);
            float O  = sig_fast(gO);
            float Ht = tanh_fast(gH);
            cReg = F * cReg + O * Ht;            // faithful: uses O, not I
            hn = O * tanh_fast(cReg);
            ho[r_e * 4 + jj_e] = hn + cw;        // tagged, gathered in SMEM
        }
        __syncwarp();

        // ---- store: one STG.128 per batch row (16B chunk atomic) -------------
        if (lane < 8) {
            float4 v = *(const float4*)&ho[lane * 4];
            __stcg((float4*)(g_Hbuf[nxt] + (rb + lane) * HDIM + j0 + 4 * wid), v);
        }
        if (t == LSEQ - 1)
            out[(rb + r_e) * HDIM + jcol] = hn;
        __syncwarp();   // ho/ws stable before next step's writes
        // Bf double-buffer: rewrite of buffer (t&1) at fill t+2 is safe —
        // sync(t+1) implies all warps completed MMA(t).
    }
}

// ---------------------------------------------------------------------------
// launcher
// ---------------------------------------------------------------------------
extern "C" void kernel_launch(void* const* d_in, const int* in_sizes, int n_in,
                              void* d_out, int out_size)
{
    (void)in_sizes; (void)n_in; (void)out_size;
    const void*  X   = d_in[0];
    const float* E   = (const float*)d_in[1];
    const float* Ww  = (const float*)d_in[2];
    const float* Wb  = (const float*)d_in[3];
    float*       out = (float*)d_out;

    split_kernel<<<8192, 256>>>(E, Ww);
    table_kernel<<<dim3(VOC / 64, G3 / 64), 256>>>(Wb);
    lstm_kernel<<<128, NT>>>(X, Ww, out);
}

// round 16
// speedup vs baseline: 1.3362x; 1.2017x over previous
#include <cuda_runtime.h>
#include <cuda_bf16.h>
#include <cstdint>

// ---------------------------------------------------------------------------
// SimpleLSTM on GB300 (plain sm_103 PTX) — round 16 = verified-best (r11):
//   - lstm: HMMA recurrence, W as register-resident bf16-split A-fragments,
//     tagged-data L2 exchange (word0 tag, 16B-atomic STG.128 producer stores,
//     coalesced 128B per-warp store pattern), interleaved B-fragments
//     (LDS.128), 2 block barriers per step, single Bf/Gsm2 buffers (safe by
//     barrier ordering).
//   - table: bf16-split HMMA GEMM; split_kernel pre-splits E / W_x once.
// ---------------------------------------------------------------------------

#define NB    128
#define LSEQ  2048
#define HDIM  256
#define EMB   256
#define VOC   32000
#define G3    768
#define NT    256

__device__ float    g_T[VOC * G3];          // token-gate table (~98.3 MB)
__device__ float    g_Hbuf[2][NB * HDIM];   // H double buffer (tagged values)
__device__ uint32_t g_EhG[VOC * 128];       // E hi split, bf16x2 words
__device__ uint32_t g_ElG[VOC * 128];       // E lo split
__device__ uint32_t g_WhG[G3 * 128];        // W_x hi split (live gate rows)
__device__ uint32_t g_WlG[G3 * 128];        // W_x lo split

// ---------------------------------------------------------------------------
// helpers
// ---------------------------------------------------------------------------
__device__ __forceinline__ float4 ldv4_volatile(const float* p)
{
    float4 v;
    asm volatile("ld.volatile.global.v4.f32 {%0, %1, %2, %3}, [%4];"
                 : "=f"(v.x), "=f"(v.y), "=f"(v.z), "=f"(v.w) : "l"(p)
                 : "memory");
    return v;
}

__device__ __forceinline__ float sig_fast(float x)
{
    return __fdividef(1.0f, 1.0f + __expf(-x));
}

__device__ __forceinline__ float tanh_fast(float x)
{
    return __fdividef(2.0f, 1.0f + __expf(-2.0f * x)) - 1.0f;
}

// split a float2 (consecutive k pair) into bf16x2 hi and lo b32 values.
__device__ __forceinline__ void split2(float2 f, uint32_t& hi, uint32_t& lo)
{
    __nv_bfloat16 h0 = __float2bfloat16_rn(f.x);
    __nv_bfloat16 h1 = __float2bfloat16_rn(f.y);
    __nv_bfloat16 l0 = __float2bfloat16_rn(f.x - __bfloat162float(h0));
    __nv_bfloat16 l1 = __float2bfloat16_rn(f.y - __bfloat162float(h1));
    __nv_bfloat162 ph = __halves2bfloat162(h0, h1);
    __nv_bfloat162 pl = __halves2bfloat162(l0, l1);
    hi = *(uint32_t*)&ph;
    lo = *(uint32_t*)&pl;
}

__device__ __forceinline__ void mma16816(float& c0, float& c1, float& c2, float& c3,
                                         uint32_t a0, uint32_t a1, uint32_t a2, uint32_t a3,
                                         uint32_t b0, uint32_t b1)
{
    asm volatile(
        "mma.sync.aligned.m16n8k16.row.col.f32.bf16.bf16.f32 "
        "{%0,%1,%2,%3}, {%4,%5,%6,%7}, {%8,%9}, {%0,%1,%2,%3};"
        : "+f"(c0), "+f"(c1), "+f"(c2), "+f"(c3)
        : "r"(a0), "r"(a1), "r"(a2), "r"(a3), "r"(b0), "r"(b1));
}

__device__ __forceinline__ int grow_of(int g)   // live-gate row -> W row
{
    int gate = g >> 8, jj = g & 255;
    return (gate == 0 ? 0 : (gate == 1 ? 512 : 768)) + jj;
}

// ---------------------------------------------------------------------------
// Kernel 0: split E and W_x (input half, live gate rows) into bf16 hi/lo.
// ---------------------------------------------------------------------------
__global__ void split_kernel(const float* __restrict__ E,
                             const float* __restrict__ Ww)
{
    int idx = blockIdx.x * 256 + threadIdx.x;
    uint32_t h0, l0, h1, l1;
    if (idx < VOC * 64) {
        int row = idx >> 6, f4 = idx & 63;
        float4 e = *(const float4*)(E + row * EMB + f4 * 4);
        split2(make_float2(e.x, e.y), h0, l0);
        split2(make_float2(e.z, e.w), h1, l1);
        *(uint2*)&g_EhG[row * 128 + f4 * 2] = make_uint2(h0, h1);
        *(uint2*)&g_ElG[row * 128 + f4 * 2] = make_uint2(l0, l1);
    } else {
        int widx = idx - VOC * 64;
        int row = widx >> 6, f4 = widx & 63;      // row = live gate idx 0..767
        int grow = grow_of(row);
        float4 w = *(const float4*)(Ww + grow * 512 + 256 + f4 * 4);
        split2(make_float2(w.x, w.y), h0, l0);
        split2(make_float2(w.z, w.w), h1, l1);
        *(uint2*)&g_WhG[row * 128 + f4 * 2] = make_uint2(h0, h1);
        *(uint2*)&g_WlG[row * 128 + f4 * 2] = make_uint2(l0, l1);
    }
}

// ---------------------------------------------------------------------------
// Kernel 1: token table GEMM via HMMA (M=32000, N=768, K=256), 64x64 tiles.
//   3-term bf16 split: EhWh + EhWl + ElWh. SMEM row stride 36 words.
// ---------------------------------------------------------------------------
__global__ void __launch_bounds__(256)
table_kernel(const float* __restrict__ Wb)
{
    __shared__ uint32_t Eh[64 * 36], El[64 * 36];
    __shared__ uint32_t Wh[64 * 36], Wl[64 * 36];

    const int tid  = threadIdx.x;
    const int v0   = blockIdx.x * 64;
    const int g0   = blockIdx.y * 64;
    const int wid  = tid >> 5, lane = tid & 31;
    const int gid  = lane >> 2, tig = lane & 3;
    const int m0   = (wid & 3) * 16;
    const int n0   = (wid >> 2) * 32;

    float acc[4][4];
#pragma unroll
    for (int i = 0; i < 4; i++)
#pragma unroll
        for (int j = 0; j < 4; j++) acc[i][j] = 0.0f;

    for (int c = 0; c < 4; c++) {          // K chunk of 64
#pragma unroll
        for (int it = 0; it < 8; it++) {
            int idx = tid + it * 256;       // 0..2047
            int buf = idx >> 9, rem = idx & 511;
            int row = rem >> 3, w4 = rem & 7;
            const uint32_t* src;
            uint32_t* dst;
            if (buf == 0)      { src = &g_EhG[(v0 + row) * 128]; dst = Eh; }
            else if (buf == 1) { src = &g_ElG[(v0 + row) * 128]; dst = El; }
            else if (buf == 2) { src = &g_WhG[(g0 + row) * 128]; dst = Wh; }
            else               { src = &g_WlG[(g0 + row) * 128]; dst = Wl; }
            uint4 v = *(const uint4*)(src + c * 32 + w4 * 4);
            *(uint4*)(dst + row * 36 + w4 * 4) = v;
        }
        __syncthreads();

#pragma unroll
        for (int ktL = 0; ktL < 4; ktL++) {
            int kw = ktL * 8 + tig;
            uint32_t ah0 = Eh[(m0 + gid) * 36 + kw];
            uint32_t ah1 = Eh[(m0 + gid + 8) * 36 + kw];
            uint32_t ah2 = Eh[(m0 + gid) * 36 + kw + 4];
            uint32_t ah3 = Eh[(m0 + gid + 8) * 36 + kw + 4];
            uint32_t al0 = El[(m0 + gid) * 36 + kw];
            uint32_t al1 = El[(m0 + gid + 8) * 36 + kw];
            uint32_t al2 = El[(m0 + gid) * 36 + kw + 4];
            uint32_t al3 = El[(m0 + gid + 8) * 36 + kw + 4];
#pragma unroll
            for (int nn = 0; nn < 4; nn++) {
                int wr = (n0 + nn * 8 + gid) * 36 + kw;
                uint32_t bh0 = Wh[wr], bh1 = Wh[wr + 4];
                uint32_t bl0 = Wl[wr], bl1 = Wl[wr + 4];
                mma16816(acc[nn][0], acc[nn][1], acc[nn][2], acc[nn][3],
                         ah0, ah1, ah2, ah3, bh0, bh1);
                mma16816(acc[nn][0], acc[nn][1], acc[nn][2], acc[nn][3],
                         ah0, ah1, ah2, ah3, bl0, bl1);
                mma16816(acc[nn][0], acc[nn][1], acc[nn][2], acc[nn][3],
                         al0, al1, al2, al3, bh0, bh1);
            }
        }
        __syncthreads();
    }

#pragma unroll
    for (int nn = 0; nn < 4; nn++) {
        int g  = g0 + n0 + nn * 8 + tig * 2;
        float b0 = Wb[grow_of(g)];
        float b1 = Wb[grow_of(g + 1)];
        int vA = v0 + m0 + gid, vB = vA + 8;
        *(float2*)&g_T[vA * G3 + g] = make_float2(acc[nn][0] + b0, acc[nn][1] + b1);
        *(float2*)&g_T[vB * G3 + g] = make_float2(acc[nn][2] + b0, acc[nn][3] + b1);
    }
}

// ---------------------------------------------------------------------------
// Kernel 2: persistent recurrence, HMMA + tagged exchange (2 syncs/step).
// ---------------------------------------------------------------------------

#define KTW 132   // words per k-tile slot (128 + 4 pad)

__global__ void __launch_bounds__(NT, 1)
lstm_kernel(const void* __restrict__ Xraw,
            const float* __restrict__ Ww,
            float* __restrict__ out)
{
    // Bf word = kt*KTW + lane*4 + q, q = reg*2 + split
    __shared__ uint32_t Bf[16 * KTW];        // 8448 B
    __shared__ float    Gsm2[96 * 9];        // G staging, stride 9 (bank-free)
    __shared__ float    Csm[256];
    __shared__ int      tokb[16];

    const int tid  = threadIdx.x;
    const int wid  = tid >> 5;
    const int lane = tid & 31;
    const int bt   = blockIdx.x >> 3;
    const int ct   = blockIdx.x & 7;
    const int rb   = bt * 8;
    const int j0   = ct * 32;

    const int gid = lane >> 2;      // mma group id
    const int tig = lane & 3;       // mma thread-in-group

    // --- int64 vs int32 token buffer detection ----------------------------
    const int* Xi = (const int*)Xraw;
    bool is64 = true;
#pragma unroll
    for (int i = 0; i < 16; i++)
        if (Xi[2 * i + 1] != 0) is64 = false;
    const long long* Xl = (const long long*)Xraw;

    // --- init: zero Bf, C; first tokens ------------------------------------
    for (int i = tid; i < 16 * KTW; i += NT) Bf[i] = 0u;
    Csm[tid] = 0.0f;
    if (tid < 8)
        tokb[tid] = is64 ? (int)Xl[(rb + tid) * LSEQ] : Xi[(rb + tid) * LSEQ];

    // --- build W A-fragments in registers (warps 0..5) ----------------------
    uint32_t A1[16][4], A2[16][4];
    if (wid < 6) {
        int m0 = wid * 16 + gid, m1 = m0 + 8;
        int ga = m0 >> 5, ja = m0 & 31;
        int gb = m1 >> 5, jb = m1 & 31;
        int grow0 = (ga == 0 ? 0 : (ga == 1 ? 512 : 768)) + j0 + ja;
        int grow1 = (gb == 0 ? 0 : (gb == 1 ? 512 : 768)) + j0 + jb;
#pragma unroll
        for (int kt = 0; kt < 16; kt++) {
            int k = kt * 16 + tig * 2;
            float2 f;
            f = __ldg((const float2*)(Ww + grow0 * 512 + k));
            split2(f, A1[kt][0], A2[kt][0]);
            f = __ldg((const float2*)(Ww + grow1 * 512 + k));
            split2(f, A1[kt][1], A2[kt][1]);
            f = __ldg((const float2*)(Ww + grow0 * 512 + k + 8));
            split2(f, A1[kt][2], A2[kt][2]);
            f = __ldg((const float2*)(Ww + grow1 * 512 + k + 8));
            split2(f, A1[kt][3], A2[kt][3]);
        }
    }
    __syncthreads();

    // --- fill mapping (all 8 warps; producer rank = wid) --------------------
    const int kq = wid;
    const int fq = lane & 7;            // k-quad within slice
    const int r0 = lane >> 3;           // batch rows 0..3 (v0)
    const int r1 = r0 + 4;              // batch rows 4..7 (v1)
    const int fkt  = kq * 2 + (fq >> 2);
    const int freg = (fq >> 1) & 1;
    const int ftig = (fq & 1) * 2;
    uint2* B2 = (uint2*)Bf;
    const int u0a = fkt * (KTW / 2) + (r0 * 4 + ftig) * 2 + freg;
    const int u0b = fkt * (KTW / 2) + (r0 * 4 + ftig + 1) * 2 + freg;
    const int u1a = fkt * (KTW / 2) + (r1 * 4 + ftig) * 2 + freg;
    const int u1b = fkt * (KTW / 2) + (r1 * 4 + ftig + 1) * 2 + freg;

    const int er = tid >> 5, ej = lane;  // epilogue element (row, col)

    for (int t = 0; t < LSEQ; t++) {
        const int cur = t & 1, nxt = cur ^ 1;

        // ---- Gx prefetch (token-determined; overlaps the poll) ------------
        const float* Tr = g_T + (long long)tokb[cur * 8 + er] * G3 + j0 + ej;
        float gxF = __ldg(Tr);
        float gxO = __ldg(Tr + 256);
        float gxH = __ldg(Tr + 512);

        if (tid < 8 && t + 1 < LSEQ)
            tokb[nxt * 8 + tid] = is64 ? (int)Xl[(rb + tid) * LSEQ + t + 1]
                                       : Xi[(rb + tid) * LSEQ + t + 1];

        // ---- fill: poll tagged H slice (self included), emit B fragments --
        if (t > 0) {
            const float cr = 4.0f + 8.0f * (float)(((t - 1) >> 1) & 3);
            const float* hb = g_Hbuf[cur];
            const float* p0 = hb + (rb + r0) * HDIM + kq * 32 + fq * 4;
            const float* p1 = hb + (rb + r1) * HDIM + kq * 32 + fq * 4;
            float4 v0, v1;
            bool d0 = false, d1 = false;
            do {
                if (!d0) { v0 = ldv4_volatile(p0); d0 = fabsf(v0.x - cr) < 2.0f; }
                if (!d1) { v1 = ldv4_volatile(p1); d1 = fabsf(v1.x - cr) < 2.0f; }
            } while (!(d0 && d1));
            v0.x -= cr; v0.y -= cr; v0.z -= cr; v0.w -= cr;
            v1.x -= cr; v1.y -= cr; v1.z -= cr; v1.w -= cr;
            uint32_t h0, l0, h1, l1;
            split2(make_float2(v0.x, v0.y), h0, l0);
            split2(make_float2(v0.z, v0.w), h1, l1);
            B2[u0a] = make_uint2(h0, l0);
            B2[u0b] = make_uint2(h1, l1);
            split2(make_float2(v1.x, v1.y), h0, l0);
            split2(make_float2(v1.z, v1.w), h1, l1);
            B2[u1a] = make_uint2(h0, l0);
            B2[u1b] = make_uint2(h1, l1);
        }
        __syncthreads();   // (1) B fragments ready

        // ---- HMMA: warps 0..5, 16 k-tiles x 3 split terms (LDS.128 B) ------
        if (wid < 6) {
            float cA0 = 0.f, cA1 = 0.f, cA2 = 0.f, cA3 = 0.f;
            float cB0 = 0.f, cB1 = 0.f, cB2 = 0.f, cB3 = 0.f;
            float cC0 = 0.f, cC1 = 0.f, cC2 = 0.f, cC3 = 0.f;
#pragma unroll
            for (int kt = 0; kt < 16; kt++) {
                uint4 b = *(const uint4*)&Bf[kt * KTW + lane * 4];
                // words: x=b1r0(hi), y=b2r0(lo), z=b1r1(hi), w=b2r1(lo)
                mma16816(cA0, cA1, cA2, cA3,
                         A1[kt][0], A1[kt][1], A1[kt][2], A1[kt][3], b.x, b.z);
                mma16816(cB0, cB1, cB2, cB3,
                         A1[kt][0], A1[kt][1], A1[kt][2], A1[kt][3], b.y, b.w);
                mma16816(cC0, cC1, cC2, cC3,
                         A2[kt][0], A2[kt][1], A2[kt][2], A2[kt][3], b.x, b.z);
            }
            int m0 = wid * 16 + gid, m1 = m0 + 8;
            Gsm2[m0 * 9 + tig * 2]     = cA0 + cB0 + cC0;
            Gsm2[m0 * 9 + tig * 2 + 1] = cA1 + cB1 + cC1;
            Gsm2[m1 * 9 + tig * 2]     = cA2 + cB2 + cC2;
            Gsm2[m1 * 9 + tig * 2 + 1] = cA3 + cB3 + cC3;
        }
        __syncthreads();   // (2) G ready

        // ---- epilogue: gates, C, H_new (tagged store) ------------------------
        {
            const float cw = 4.0f + 8.0f * (float)((t >> 1) & 3);
            float gF = gxF + Gsm2[ej * 9 + er];
            float gO = gxO + Gsm2[(32 + ej) * 9 + er];
            float gH = gxH + Gsm2[(64 + ej) * 9 + er];
            float F  = sig_fast(gF);
            float O  = sig_fast(gO);
            float Ht = tanh_fast(gH);
            float c  = F * Csm[tid] + O * Ht;      // faithful: uses O, not I
            Csm[tid] = c;
            float hn = O * tanh_fast(c);
            __stcg(g_Hbuf[nxt] + (rb + er) * HDIM + j0 + ej, hn + cw);
            if (t == LSEQ - 1)
                out[(rb + er) * HDIM + j0 + ej] = hn;
        }
        // no third sync: Bf next write fenced by (2); Gsm2 next write by (1)
    }
}

// ---------------------------------------------------------------------------
// launcher
// ---------------------------------------------------------------------------
extern "C" void kernel_launch(void* const* d_in, const int* in_sizes, int n_in,
                              void* d_out, int out_size)
{
    (void)in_sizes; (void)n_in; (void)out_size;
    const void*  X   = d_in[0];
    const float* E   = (const float*)d_in[1];
    const float* Ww  = (const float*)d_in[2];
    const float* Wb  = (const float*)d_in[3];
    float*       out = (float*)d_out;

    split_kernel<<<8192, 256>>>(E, Ww);
    table_kernel<<<dim3(VOC / 64, G3 / 64), 256>>>(Wb);
    lstm_kernel<<<128, NT>>>(X, Ww, out);
}